// round 1
// baseline (speedup 1.0000x reference)
#include <cuda_runtime.h>

// QuantizedTopKSparsity — mathematically reduces to:
//   out[r, c] = rint( x[r, c] / (max_c |x[r, c]| + 1e-6) )
// because the quantized values lie in {-1, 0, +1}, making the top-k mask an
// identity on x_q (see analysis: thresh is 0 or 1; x_q * mask == x_q in both cases).
//
// One CTA per row: 256 threads x 16 floats (4x float4) held in registers,
// block absmax reduction, then rint(x * rcp) written back. Single GMEM pass.

#define ROW_LEN 4096
#define THREADS 256
#define V4_PER_THREAD 4   // 4 float4 = 16 floats per thread; 256*16 = 4096

__global__ __launch_bounds__(THREADS)
void qtopk_kernel(const float* __restrict__ x, float* __restrict__ out, int rows) {
    const int row = blockIdx.x;
    if (row >= rows) return;

    const float4* __restrict__ xr =
        reinterpret_cast<const float4*>(x + (size_t)row * ROW_LEN);
    float4* __restrict__ orow =
        reinterpret_cast<float4*>(out + (size_t)row * ROW_LEN);

    const int t = threadIdx.x;

    // Load 4 float4 per thread, coalesced stripes, accumulate absmax.
    float4 v[V4_PER_THREAD];
    float m = 0.0f;
#pragma unroll
    for (int i = 0; i < V4_PER_THREAD; i++) {
        v[i] = xr[t + i * THREADS];
        m = fmaxf(m, fmaxf(fmaxf(fabsf(v[i].x), fabsf(v[i].y)),
                           fmaxf(fabsf(v[i].z), fabsf(v[i].w))));
    }

    // Warp absmax
#pragma unroll
    for (int o = 16; o > 0; o >>= 1)
        m = fmaxf(m, __shfl_xor_sync(0xffffffffu, m, o));

    // Cross-warp absmax via smem (8 warps)
    __shared__ float smax[THREADS / 32];
    if ((t & 31) == 0) smax[t >> 5] = m;
    __syncthreads();

    float g = smax[0];
#pragma unroll
    for (int w = 1; w < THREADS / 32; w++) g = fmaxf(g, smax[w]);

    const float inv = 1.0f / (g + 1e-6f);

    // Quantize from registers (no reload) and store.
#pragma unroll
    for (int i = 0; i < V4_PER_THREAD; i++) {
        float4 o;
        o.x = rintf(v[i].x * inv);
        o.y = rintf(v[i].y * inv);
        o.z = rintf(v[i].z * inv);
        o.w = rintf(v[i].w * inv);
        orow[t + i * THREADS] = o;
    }
}

extern "C" void kernel_launch(void* const* d_in, const int* in_sizes, int n_in,
                              void* d_out, int out_size) {
    const float* x = (const float*)d_in[0];
    float* out = (float*)d_out;
    const int rows = in_sizes[0] / ROW_LEN;   // 8192
    qtopk_kernel<<<rows, THREADS>>>(x, out, rows);
}